// round 1
// baseline (speedup 1.0000x reference)
#include <cuda_runtime.h>
#include <math.h>

#define NTOK 512
#define H    12
#define CH   16
#define CZ   128
#define CS   384
#define CATD 2112   // H*(CH + PV*3 + PV + CZ) = 12*176

// ---------------- scratch (device globals; no allocation allowed) ----------------
__device__ float g_q   [NTOK * H * CH];      // [n][h*16+c]
__device__ float g_k   [NTOK * H * CH];
__device__ float g_v   [NTOK * H * CH];
__device__ float g_qpts[NTOK * H * 4 * 3];   // [n][(h*4+p)*3 + x]  (global frame)
__device__ float g_kpts[NTOK * H * 4 * 3];
__device__ float g_vpts[NTOK * H * 8 * 3];   // [n][(h*8+p)*3 + x]
__device__ float g_cat [NTOK * CATD];        // concat features per token

// =================================================================================
// Kernel A: all input projections + rigid-frame rotation of the points.
// 4 tokens per block (amortizes W reads through L2 4x). 128 blocks x 384 threads.
// =================================================================================
__global__ __launch_bounds__(384) void proj_kernel(
    const float* __restrict__ s,  const float* __restrict__ tt, const float* __restrict__ tr,
    const float* __restrict__ Wq, const float* __restrict__ bq,
    const float* __restrict__ Wkv,const float* __restrict__ bkv,
    const float* __restrict__ Wqp,const float* __restrict__ bqp,
    const float* __restrict__ Wkvp,const float* __restrict__ bkvp)
{
    __shared__ float ssh[CS * 4];        // [k][m] layout -> float4 per k
    __shared__ float rawsh[4 * 1152];    // per-token raw projections
    const int n0 = blockIdx.x * 4;
    const int t  = threadIdx.x;

    for (int idx = t; idx < 4 * CS; idx += 384) {
        int m = idx / CS, k = idx - m * CS;
        ssh[k * 4 + m] = s[(n0 + m) * CS + k];
    }
    __syncthreads();

    const float4* s4 = (const float4*)ssh;
    #pragma unroll
    for (int p = 0; p < 3; p++) {
        int o = p * 384 + t;               // 0..1151: [Wq 192 | Wkv 384 | Wqp 144 | Wkvp 432]
        const float* W; const float* bias; int col, width;
        if      (o < 192) { W = Wq;   bias = bq;   col = o;       width = 192; }
        else if (o < 576) { W = Wkv;  bias = bkv;  col = o - 192; width = 384; }
        else if (o < 720) { W = Wqp;  bias = bqp;  col = o - 576; width = 144; }
        else              { W = Wkvp; bias = bkvp; col = o - 720; width = 432; }
        float b0 = bias[col];
        float a0 = b0, a1 = b0, a2 = b0, a3 = b0;
        const float* Wc = W + col;
        #pragma unroll 4
        for (int k = 0; k < CS; k++) {
            float w = Wc[k * width];
            float4 sv = s4[k];
            a0 += sv.x * w; a1 += sv.y * w; a2 += sv.z * w; a3 += sv.w * w;
        }
        rawsh[0*1152 + o] = a0; rawsh[1*1152 + o] = a1;
        rawsh[2*1152 + o] = a2; rawsh[3*1152 + o] = a3;
    }
    __syncthreads();

    for (int m = 0; m < 4; m++) {
        const int n = n0 + m;
        const float* raw = rawsh + m * 1152;
        if (t < 192) {
            g_q[n*192 + t] = raw[t];
            int h = t >> 4, c = t & 15;
            g_k[n*192 + t] = raw[192 + h*32 + c];
            g_v[n*192 + t] = raw[192 + h*32 + 16 + c];
        } else if (t < 240) {
            int p = t - 192;   // 0..47 : q_pts point (h*4+pq)
            float lx = raw[576 + p], ly = raw[576 + 48 + p], lz = raw[576 + 96 + p];
            const float* R = tr + n*9; const float* T = tt + n*3;
            float gx = R[0]*lx + R[1]*ly + R[2]*lz + T[0];
            float gy = R[3]*lx + R[4]*ly + R[5]*lz + T[1];
            float gz = R[6]*lx + R[7]*ly + R[8]*lz + T[2];
            g_qpts[n*144 + p*3 + 0] = gx;
            g_qpts[n*144 + p*3 + 1] = gy;
            g_qpts[n*144 + p*3 + 2] = gz;
        } else {
            int p = t - 240;   // 0..143 : kvp point (h*12+pp)
            float lx = raw[720 + p], ly = raw[720 + 144 + p], lz = raw[720 + 288 + p];
            const float* R = tr + n*9; const float* T = tt + n*3;
            float gx = R[0]*lx + R[1]*ly + R[2]*lz + T[0];
            float gy = R[3]*lx + R[4]*ly + R[5]*lz + T[1];
            float gz = R[6]*lx + R[7]*ly + R[8]*lz + T[2];
            int h = p / 12, pp = p - h*12;
            if (pp < 4) {
                int o = (h*4 + pp) * 3;
                g_kpts[n*144 + o] = gx; g_kpts[n*144 + o + 1] = gy; g_kpts[n*144 + o + 2] = gz;
            } else {
                int o = (h*8 + pp - 4) * 3;
                g_vpts[n*288 + o] = gx; g_vpts[n*288 + o + 1] = gy; g_vpts[n*288 + o + 2] = gz;
            }
        }
    }
}

// =================================================================================
// Kernel B: fused attention. One block per query row i (512 blocks x 384 threads).
// Phase 1 : logits for all 12 heads, 32 j per chunk (z chunk in smem -> bias GEMM
//           fused here so z is read from DRAM exactly once per block slice)
// Phase 2 : per-head softmax (warp h owns head h)
// Phase 3 : o, o_pt (+inverse rotation, norms), o_pair (second z pass; L2-resident)
// Static smem = exactly 49152 B.
// =================================================================================
// smem float offsets
#define SMO_A   0        // a[12][512]                                  6144
#define SMO_Z   6144     // z chunk [32][132]  (pad->conflict-free)     4224   (reused as optsh)
#define SMO_WB  10368    // Wb^T [12][132]; [h][128]=hw, [h][129]=bb    1584
#define SMO_Q   11952    // q_i [192]
#define SMO_QP  12144    // q_pts_i [144]
#define SMO_TOT 12288    // = 49152 bytes

__global__ __launch_bounds__(384) void attn_kernel(
    const float* __restrict__ z,   const float* __restrict__ msk,
    const float* __restrict__ Wb,  const float* __restrict__ bb,
    const float* __restrict__ hwts,const float* __restrict__ tt,
    const float* __restrict__ tr)
{
    __shared__ float sm[SMO_TOT];
    float* a_sh  = sm + SMO_A;
    float* zsh   = sm + SMO_Z;
    float* wbt   = sm + SMO_WB;
    float* qsh   = sm + SMO_Q;
    float* qpsh  = sm + SMO_QP;
    float* optsh = zsh;                 // reuse after phase 1

    const int i = blockIdx.x, t = threadIdx.x;

    if (t < 192) qsh[t]  = g_q[i*192 + t];
    if (t < 144) qpsh[t] = g_qpts[i*144 + t];
    for (int idx = t; idx < 1536; idx += 384) {      // Wb (128x12) -> wbt[h][kk]
        int kk = idx / 12, h = idx - kk * 12;
        wbt[h*132 + kk] = Wb[idx];
    }
    if (t < 12) {
        float x = hwts[t];
        float sp = (x > 20.f) ? x : log1pf(__expf(x));
        wbt[t*132 + 128] = sp * 0.13608276348795434f;  // sqrt(1/54)
        wbt[t*132 + 129] = bb[t];
    }
    const float mask_i = msk[i];
    __syncthreads();

    const float qk_scale = 0.14433756729740643f;  // 1/sqrt(48)
    const float c2       = 0.57735026918962584f;  // 1/sqrt(3)
    const size_t zbase = (size_t)i * NTOK * CZ;

    const int jj = t / 12, h = t - jj * 12;       // 384 = 32*12 exactly

    // ---- Phase 1: logits ----
    for (int j0 = 0; j0 < NTOK; j0 += 32) {
        for (int idx = t; idx < 32 * 128; idx += 384) {
            int r = idx >> 7, c = idx & 127;
            zsh[r*132 + c] = z[zbase + (size_t)(j0 + r) * 128 + c];
        }
        __syncthreads();

        const int j = j0 + jj;
        float bacc = 0.f;
        const float4* zr = (const float4*)(zsh + jj*132);
        const float4* wr = (const float4*)(wbt + h*132);
        #pragma unroll 8
        for (int k4 = 0; k4 < 32; k4++) {
            float4 zv = zr[k4], wv = wr[k4];
            bacc += zv.x*wv.x; bacc += zv.y*wv.y; bacc += zv.z*wv.z; bacc += zv.w*wv.w;
        }
        bacc += wbt[h*132 + 129];                   // + bb[h]

        float qk = 0.f;
        const float* kr = g_k + j*192 + h*16;
        const float* qr = qsh + h*16;
        #pragma unroll
        for (int c = 0; c < 16; c++) qk += qr[c] * kr[c];

        float d2 = 0.f;
        const float* kp = g_kpts + j*144 + h*12;
        const float* qp = qpsh + h*12;
        #pragma unroll
        for (int p = 0; p < 12; p++) { float d = qp[p] - kp[p]; d2 += d * d; }

        float logit = qk * qk_scale + c2 * bacc
                    - 0.5f * wbt[h*132 + 128] * d2
                    + 100000.0f * (mask_i * msk[j] - 1.0f);
        a_sh[h*512 + j] = logit;
        __syncthreads();
    }

    // ---- Phase 2: softmax (warp w owns head w; 12 warps total) ----
    {
        const int w = t >> 5, lane = t & 31;
        float* row = a_sh + w * 512;
        float mx = -1e30f;
        for (int j = lane; j < 512; j += 32) mx = fmaxf(mx, row[j]);
        #pragma unroll
        for (int o = 16; o; o >>= 1) mx = fmaxf(mx, __shfl_xor_sync(0xffffffffu, mx, o));
        float ssum = 0.f;
        for (int j = lane; j < 512; j += 32) { float e = __expf(row[j] - mx); row[j] = e; ssum += e; }
        #pragma unroll
        for (int o = 16; o; o >>= 1) ssum += __shfl_xor_sync(0xffffffffu, ssum, o);
        float inv = 1.0f / ssum;
        for (int j = lane; j < 512; j += 32) row[j] *= inv;
    }
    __syncthreads();

    // ---- Phase 3a: o (192 outputs) and raw o_pt sums (288) ----
    #pragma unroll
    for (int r = 0; r < 2; r++) {
        const int idx = r * 384 + t;
        if (idx < 192) {
            int hh = idx >> 4, c = idx & 15;
            const float* ar = a_sh + hh * 512;
            const float* vc = g_v + hh*16 + c;
            float acc = 0.f;
            for (int j = 0; j < 512; j++) acc += ar[j] * vc[j * 192];
            g_cat[i*CATD + idx] = acc;
        } else if (idx < 480) {
            int m  = idx - 192;
            int hh = m / 24, rem = m - hh * 24;    // rem = p*3+x
            const float* ar = a_sh + hh * 512;
            const float* vc = g_vpts + hh*24 + rem;
            float acc = 0.f;
            for (int j = 0; j < 512; j++) acc += ar[j] * vc[j * 288];
            optsh[m] = acc;
        }
    }
    __syncthreads();

    // ---- Phase 3b: inverse rigid transform + norms (96 points) ----
    if (t < 96) {
        float gx = optsh[t*3], gy = optsh[t*3 + 1], gz = optsh[t*3 + 2];
        const float* R = tr + i*9; const float* T = tt + i*3;
        float dx = gx - T[0], dy = gy - T[1], dz = gz - T[2];
        float lx = R[0]*dx + R[3]*dy + R[6]*dz;   // R^T * d
        float ly = R[1]*dx + R[4]*dy + R[7]*dz;
        float lz = R[2]*dx + R[5]*dy + R[8]*dz;
        float* cr = g_cat + i*CATD;
        cr[192 + t] = lx; cr[288 + t] = ly; cr[384 + t] = lz;
        cr[480 + t] = sqrtf(lx*lx + ly*ly + lz*lz + 1e-8f);
    }

    // ---- Phase 3c: o_pair (second z pass, 4 heads per thread) ----
    {
        const int c = t & 127, hb = t >> 7;           // hb in 0..2
        const float* zp = z + zbase + c;
        const float* a0 = a_sh + (hb + 0) * 512;
        const float* a1 = a_sh + (hb + 3) * 512;
        const float* a2 = a_sh + (hb + 6) * 512;
        const float* a3 = a_sh + (hb + 9) * 512;
        float s0 = 0.f, s1 = 0.f, s2 = 0.f, s3 = 0.f;
        for (int j = 0; j < 512; j++) {
            float zv = zp[(size_t)j * 128];
            s0 += a0[j]*zv; s1 += a1[j]*zv; s2 += a2[j]*zv; s3 += a3[j]*zv;
        }
        float* cr = g_cat + i*CATD + 576;
        cr[(hb + 0)*128 + c] = s0; cr[(hb + 3)*128 + c] = s1;
        cr[(hb + 6)*128 + c] = s2; cr[(hb + 9)*128 + c] = s3;
    }
}

// =================================================================================
// Kernel C0: out = bout (bias init, atomics target)
// =================================================================================
__global__ void init_out_kernel(const float* __restrict__ bout, float* __restrict__ out)
{
    out[blockIdx.x * 384 + threadIdx.x] = bout[threadIdx.x];
}

// =================================================================================
// Kernel C1: out += cat @ Wout.  split-k=4 x 32 row-tiles (16 rows) = 128 blocks.
// cat tile transposed in smem -> broadcast LDS.128; W reads fully coalesced.
// =================================================================================
__global__ __launch_bounds__(384) void out_gemm_kernel(
    const float* __restrict__ Wout, float* __restrict__ out)
{
    __shared__ float csh[528 * 16];     // [kk][m]
    const int bx = blockIdx.x;
    const int rt = bx & 31, ks = bx >> 5;
    const int i0 = rt * 16, k0 = ks * 528;
    const int t  = threadIdx.x;

    for (int idx = t; idx < 528 * 16; idx += 384) {
        int row = idx / 528, kk = idx - row * 528;
        csh[kk*16 + row] = g_cat[(i0 + row) * CATD + k0 + kk];
    }
    __syncthreads();

    float acc[16];
    #pragma unroll
    for (int m = 0; m < 16; m++) acc[m] = 0.f;

    const float* Wp = Wout + (size_t)k0 * 384 + t;
    for (int kk = 0; kk < 528; kk++) {
        float w = Wp[(size_t)kk * 384];
        const float4* cp = (const float4*)(csh + kk * 16);
        float4 c0 = cp[0], c1 = cp[1], c2 = cp[2], c3 = cp[3];
        acc[0]  += c0.x*w; acc[1]  += c0.y*w; acc[2]  += c0.z*w; acc[3]  += c0.w*w;
        acc[4]  += c1.x*w; acc[5]  += c1.y*w; acc[6]  += c1.z*w; acc[7]  += c1.w*w;
        acc[8]  += c2.x*w; acc[9]  += c2.y*w; acc[10] += c2.z*w; acc[11] += c2.w*w;
        acc[12] += c3.x*w; acc[13] += c3.y*w; acc[14] += c3.z*w; acc[15] += c3.w*w;
    }
    #pragma unroll
    for (int m = 0; m < 16; m++)
        atomicAdd(&out[(i0 + m) * 384 + t], acc[m]);
}

// =================================================================================
extern "C" void kernel_launch(void* const* d_in, const int* in_sizes, int n_in,
                              void* d_out, int out_size)
{
    (void)in_sizes; (void)n_in; (void)out_size;
    const float* s    = (const float*)d_in[0];
    const float* z    = (const float*)d_in[1];
    const float* tt   = (const float*)d_in[2];
    const float* tr   = (const float*)d_in[3];
    const float* mask = (const float*)d_in[4];
    const float* Wq   = (const float*)d_in[5];
    const float* bq   = (const float*)d_in[6];
    const float* Wkv  = (const float*)d_in[7];
    const float* bkv  = (const float*)d_in[8];
    const float* Wqp  = (const float*)d_in[9];
    const float* bqp  = (const float*)d_in[10];
    const float* Wkvp = (const float*)d_in[11];
    const float* bkvp = (const float*)d_in[12];
    const float* Wb   = (const float*)d_in[13];
    const float* bb   = (const float*)d_in[14];
    const float* hwts = (const float*)d_in[15];
    const float* Wout = (const float*)d_in[16];
    const float* bout = (const float*)d_in[17];
    float* out = (float*)d_out;

    proj_kernel<<<128, 384>>>(s, tt, tr, Wq, bq, Wkv, bkv, Wqp, bqp, Wkvp, bkvp);
    attn_kernel<<<512, 384>>>(z, mask, Wb, bb, hwts, tt, tr);
    init_out_kernel<<<512, 384>>>(bout, out);
    out_gemm_kernel<<<128, 384>>>(Wout, out);
}

// round 2
// speedup vs baseline: 1.0088x; 1.0088x over previous
#include <cuda_runtime.h>
#include <math.h>

#define NTOK 512
#define H    12
#define CH   16
#define CZ   128
#define CS   384
#define CATD 2112   // H*(CH + PV*3 + PV + CZ) = 12*176

// ---------------- scratch (device globals; no allocation allowed) ----------------
__device__ float g_q   [NTOK * H * CH];      // [n][h*16+c]
__device__ float g_k   [NTOK * H * CH];
__device__ float g_v   [NTOK * H * CH];
__device__ float g_qpts[NTOK * H * 4 * 3];   // [n][(h*4+p)*3 + x]  (global frame)
__device__ float g_kpts[NTOK * H * 4 * 3];
__device__ float g_vpts[NTOK * H * 8 * 3];   // [n][(h*8+p)*3 + x]
__device__ float g_cat [NTOK * CATD];        // concat features per token

// =================================================================================
// Kernel A: all input projections + rigid-frame rotation of the points.
// 4 tokens per block (amortizes W reads through L2 4x). 128 blocks x 384 threads.
// =================================================================================
__global__ __launch_bounds__(384) void proj_kernel(
    const float* __restrict__ s,  const float* __restrict__ tt, const float* __restrict__ tr,
    const float* __restrict__ Wq, const float* __restrict__ bq,
    const float* __restrict__ Wkv,const float* __restrict__ bkv,
    const float* __restrict__ Wqp,const float* __restrict__ bqp,
    const float* __restrict__ Wkvp,const float* __restrict__ bkvp)
{
    __shared__ float ssh[CS * 4];        // [k][m] layout -> float4 per k
    __shared__ float rawsh[4 * 1152];    // per-token raw projections
    const int n0 = blockIdx.x * 4;
    const int t  = threadIdx.x;

    for (int idx = t; idx < 4 * CS; idx += 384) {
        int m = idx / CS, k = idx - m * CS;
        ssh[k * 4 + m] = s[(n0 + m) * CS + k];
    }
    __syncthreads();

    const float4* s4 = (const float4*)ssh;
    #pragma unroll
    for (int p = 0; p < 3; p++) {
        int o = p * 384 + t;               // 0..1151: [Wq 192 | Wkv 384 | Wqp 144 | Wkvp 432]
        const float* W; const float* bias; int col, width;
        if      (o < 192) { W = Wq;   bias = bq;   col = o;       width = 192; }
        else if (o < 576) { W = Wkv;  bias = bkv;  col = o - 192; width = 384; }
        else if (o < 720) { W = Wqp;  bias = bqp;  col = o - 576; width = 144; }
        else              { W = Wkvp; bias = bkvp; col = o - 720; width = 432; }
        float b0 = bias[col];
        float a0 = b0, a1 = b0, a2 = b0, a3 = b0;
        const float* Wc = W + col;
        #pragma unroll 4
        for (int k = 0; k < CS; k++) {
            float w = Wc[k * width];
            float4 sv = s4[k];
            a0 += sv.x * w; a1 += sv.y * w; a2 += sv.z * w; a3 += sv.w * w;
        }
        rawsh[0*1152 + o] = a0; rawsh[1*1152 + o] = a1;
        rawsh[2*1152 + o] = a2; rawsh[3*1152 + o] = a3;
    }
    __syncthreads();

    for (int m = 0; m < 4; m++) {
        const int n = n0 + m;
        const float* raw = rawsh + m * 1152;
        if (t < 192) {
            g_q[n*192 + t] = raw[t];
            int h = t >> 4, c = t & 15;
            g_k[n*192 + t] = raw[192 + h*32 + c];
            g_v[n*192 + t] = raw[192 + h*32 + 16 + c];
        } else if (t < 240) {
            int p = t - 192;   // 0..47 : q_pts point (h*4+pq)
            float lx = raw[576 + p], ly = raw[576 + 48 + p], lz = raw[576 + 96 + p];
            const float* R = tr + n*9; const float* T = tt + n*3;
            float gx = R[0]*lx + R[1]*ly + R[2]*lz + T[0];
            float gy = R[3]*lx + R[4]*ly + R[5]*lz + T[1];
            float gz = R[6]*lx + R[7]*ly + R[8]*lz + T[2];
            g_qpts[n*144 + p*3 + 0] = gx;
            g_qpts[n*144 + p*3 + 1] = gy;
            g_qpts[n*144 + p*3 + 2] = gz;
        } else {
            int p = t - 240;   // 0..143 : kvp point (h*12+pp)
            float lx = raw[720 + p], ly = raw[720 + 144 + p], lz = raw[720 + 288 + p];
            const float* R = tr + n*9; const float* T = tt + n*3;
            float gx = R[0]*lx + R[1]*ly + R[2]*lz + T[0];
            float gy = R[3]*lx + R[4]*ly + R[5]*lz + T[1];
            float gz = R[6]*lx + R[7]*ly + R[8]*lz + T[2];
            int h = p / 12, pp = p - h*12;
            if (pp < 4) {
                int o = (h*4 + pp) * 3;
                g_kpts[n*144 + o] = gx; g_kpts[n*144 + o + 1] = gy; g_kpts[n*144 + o + 2] = gz;
            } else {
                int o = (h*8 + pp - 4) * 3;
                g_vpts[n*288 + o] = gx; g_vpts[n*288 + o + 1] = gy; g_vpts[n*288 + o + 2] = gz;
            }
        }
    }
}

// =================================================================================
// Kernel B: fused attention. One block per query row i (512 blocks x 384 threads).
// Phase 1 : logits for all 12 heads, 32 j per chunk (z chunk in smem -> bias GEMM
//           fused here so z is read from DRAM exactly once per block slice)
// Phase 2 : per-head softmax (warp h owns head h)
// Phase 3 : o, o_pt (+inverse rotation, norms), o_pair (second z pass; L2-resident)
// Static smem = exactly 49152 B.
// =================================================================================
// smem float offsets
#define SMO_A   0        // a[12][512]                                  6144
#define SMO_Z   6144     // z chunk [32][132]  (pad->conflict-free)     4224   (reused as optsh)
#define SMO_WB  10368    // Wb^T [12][132]; [h][128]=hw, [h][129]=bb    1584
#define SMO_Q   11952    // q_i [192]
#define SMO_QP  12144    // q_pts_i [144]
#define SMO_TOT 12288    // = 49152 bytes

__global__ __launch_bounds__(384) void attn_kernel(
    const float* __restrict__ z,   const float* __restrict__ msk,
    const float* __restrict__ Wb,  const float* __restrict__ bb,
    const float* __restrict__ hwts,const float* __restrict__ tt,
    const float* __restrict__ tr)
{
    __shared__ float sm[SMO_TOT];
    float* a_sh  = sm + SMO_A;
    float* zsh   = sm + SMO_Z;
    float* wbt   = sm + SMO_WB;
    float* qsh   = sm + SMO_Q;
    float* qpsh  = sm + SMO_QP;
    float* optsh = zsh;                 // reuse after phase 1

    const int i = blockIdx.x, t = threadIdx.x;

    if (t < 192) qsh[t]  = g_q[i*192 + t];
    if (t < 144) qpsh[t] = g_qpts[i*144 + t];
    for (int idx = t; idx < 1536; idx += 384) {      // Wb (128x12) -> wbt[h][kk]
        int kk = idx / 12, h = idx - kk * 12;
        wbt[h*132 + kk] = Wb[idx];
    }
    if (t < 12) {
        float x = hwts[t];
        float sp = (x > 20.f) ? x : log1pf(__expf(x));
        wbt[t*132 + 128] = sp * 0.13608276348795434f;  // sqrt(1/54)
        wbt[t*132 + 129] = bb[t];
    }
    const float mask_i = msk[i];
    __syncthreads();

    const float qk_scale = 0.14433756729740643f;  // 1/sqrt(48)
    const float c2       = 0.57735026918962584f;  // 1/sqrt(3)
    const size_t zbase = (size_t)i * NTOK * CZ;

    const int jj = t / 12, h = t - jj * 12;       // 384 = 32*12 exactly

    // ---- Phase 1: logits ----
    for (int j0 = 0; j0 < NTOK; j0 += 32) {
        for (int idx = t; idx < 32 * 128; idx += 384) {
            int r = idx >> 7, c = idx & 127;
            zsh[r*132 + c] = z[zbase + (size_t)(j0 + r) * 128 + c];
        }
        __syncthreads();

        const int j = j0 + jj;
        float bacc = 0.f;
        const float4* zr = (const float4*)(zsh + jj*132);
        const float4* wr = (const float4*)(wbt + h*132);
        #pragma unroll 8
        for (int k4 = 0; k4 < 32; k4++) {
            float4 zv = zr[k4], wv = wr[k4];
            bacc += zv.x*wv.x; bacc += zv.y*wv.y; bacc += zv.z*wv.z; bacc += zv.w*wv.w;
        }
        bacc += wbt[h*132 + 129];                   // + bb[h]

        float qk = 0.f;
        const float* kr = g_k + j*192 + h*16;
        const float* qr = qsh + h*16;
        #pragma unroll
        for (int c = 0; c < 16; c++) qk += qr[c] * kr[c];

        float d2 = 0.f;
        const float* kp = g_kpts + j*144 + h*12;
        const float* qp = qpsh + h*12;
        #pragma unroll
        for (int p = 0; p < 12; p++) { float d = qp[p] - kp[p]; d2 += d * d; }

        float logit = qk * qk_scale + c2 * bacc
                    - 0.5f * wbt[h*132 + 128] * d2
                    + 100000.0f * (mask_i * msk[j] - 1.0f);
        a_sh[h*512 + j] = logit;
        __syncthreads();
    }

    // ---- Phase 2: softmax (warp w owns head w; 12 warps total) ----
    {
        const int w = t >> 5, lane = t & 31;
        float* row = a_sh + w * 512;
        float mx = -1e30f;
        for (int j = lane; j < 512; j += 32) mx = fmaxf(mx, row[j]);
        #pragma unroll
        for (int o = 16; o; o >>= 1) mx = fmaxf(mx, __shfl_xor_sync(0xffffffffu, mx, o));
        float ssum = 0.f;
        for (int j = lane; j < 512; j += 32) { float e = __expf(row[j] - mx); row[j] = e; ssum += e; }
        #pragma unroll
        for (int o = 16; o; o >>= 1) ssum += __shfl_xor_sync(0xffffffffu, ssum, o);
        float inv = 1.0f / ssum;
        for (int j = lane; j < 512; j += 32) row[j] *= inv;
    }
    __syncthreads();

    // ---- Phase 3a: o (192 outputs) and raw o_pt sums (288) ----
    #pragma unroll
    for (int r = 0; r < 2; r++) {
        const int idx = r * 384 + t;
        if (idx < 192) {
            int hh = idx >> 4, c = idx & 15;
            const float* ar = a_sh + hh * 512;
            const float* vc = g_v + hh*16 + c;
            float acc = 0.f;
            for (int j = 0; j < 512; j++) acc += ar[j] * vc[j * 192];
            g_cat[i*CATD + idx] = acc;
        } else if (idx < 480) {
            int m  = idx - 192;
            int hh = m / 24, rem = m - hh * 24;    // rem = p*3+x
            const float* ar = a_sh + hh * 512;
            const float* vc = g_vpts + hh*24 + rem;
            float acc = 0.f;
            for (int j = 0; j < 512; j++) acc += ar[j] * vc[j * 288];
            optsh[m] = acc;
        }
    }
    __syncthreads();

    // ---- Phase 3b: inverse rigid transform + norms (96 points) ----
    if (t < 96) {
        float gx = optsh[t*3], gy = optsh[t*3 + 1], gz = optsh[t*3 + 2];
        const float* R = tr + i*9; const float* T = tt + i*3;
        float dx = gx - T[0], dy = gy - T[1], dz = gz - T[2];
        float lx = R[0]*dx + R[3]*dy + R[6]*dz;   // R^T * d
        float ly = R[1]*dx + R[4]*dy + R[7]*dz;
        float lz = R[2]*dx + R[5]*dy + R[8]*dz;
        float* cr = g_cat + i*CATD;
        cr[192 + t] = lx; cr[288 + t] = ly; cr[384 + t] = lz;
        cr[480 + t] = sqrtf(lx*lx + ly*ly + lz*lz + 1e-8f);
    }

    // ---- Phase 3c: o_pair (second z pass, 4 heads per thread) ----
    {
        const int c = t & 127, hb = t >> 7;           // hb in 0..2
        const float* zp = z + zbase + c;
        const float* a0 = a_sh + (hb + 0) * 512;
        const float* a1 = a_sh + (hb + 3) * 512;
        const float* a2 = a_sh + (hb + 6) * 512;
        const float* a3 = a_sh + (hb + 9) * 512;
        float s0 = 0.f, s1 = 0.f, s2 = 0.f, s3 = 0.f;
        for (int j = 0; j < 512; j++) {
            float zv = zp[(size_t)j * 128];
            s0 += a0[j]*zv; s1 += a1[j]*zv; s2 += a2[j]*zv; s3 += a3[j]*zv;
        }
        float* cr = g_cat + i*CATD + 576;
        cr[(hb + 0)*128 + c] = s0; cr[(hb + 3)*128 + c] = s1;
        cr[(hb + 6)*128 + c] = s2; cr[(hb + 9)*128 + c] = s3;
    }
}

// =================================================================================
// Kernel C0: out = bout (bias init, atomics target)
// =================================================================================
__global__ void init_out_kernel(const float* __restrict__ bout, float* __restrict__ out)
{
    out[blockIdx.x * 384 + threadIdx.x] = bout[threadIdx.x];
}

// =================================================================================
// Kernel C1: out += cat @ Wout.  split-k=4 x 32 row-tiles (16 rows) = 128 blocks.
// cat tile transposed in smem -> broadcast LDS.128; W reads fully coalesced.
// =================================================================================
__global__ __launch_bounds__(384) void out_gemm_kernel(
    const float* __restrict__ Wout, float* __restrict__ out)
{
    __shared__ float csh[528 * 16];     // [kk][m]
    const int bx = blockIdx.x;
    const int rt = bx & 31, ks = bx >> 5;
    const int i0 = rt * 16, k0 = ks * 528;
    const int t  = threadIdx.x;

    for (int idx = t; idx < 528 * 16; idx += 384) {
        int row = idx / 528, kk = idx - row * 528;
        csh[kk*16 + row] = g_cat[(i0 + row) * CATD + k0 + kk];
    }
    __syncthreads();

    float acc[16];
    #pragma unroll
    for (int m = 0; m < 16; m++) acc[m] = 0.f;

    const float* Wp = Wout + (size_t)k0 * 384 + t;
    for (int kk = 0; kk < 528; kk++) {
        float w = Wp[(size_t)kk * 384];
        const float4* cp = (const float4*)(csh + kk * 16);
        float4 c0 = cp[0], c1 = cp[1], c2 = cp[2], c3 = cp[3];
        acc[0]  += c0.x*w; acc[1]  += c0.y*w; acc[2]  += c0.z*w; acc[3]  += c0.w*w;
        acc[4]  += c1.x*w; acc[5]  += c1.y*w; acc[6]  += c1.z*w; acc[7]  += c1.w*w;
        acc[8]  += c2.x*w; acc[9]  += c2.y*w; acc[10] += c2.z*w; acc[11] += c2.w*w;
        acc[12] += c3.x*w; acc[13] += c3.y*w; acc[14] += c3.z*w; acc[15] += c3.w*w;
    }
    #pragma unroll
    for (int m = 0; m < 16; m++)
        atomicAdd(&out[(i0 + m) * 384 + t], acc[m]);
}

// =================================================================================
extern "C" void kernel_launch(void* const* d_in, const int* in_sizes, int n_in,
                              void* d_out, int out_size)
{
    (void)in_sizes; (void)n_in; (void)out_size;
    const float* s    = (const float*)d_in[0];
    const float* z    = (const float*)d_in[1];
    const float* tt   = (const float*)d_in[2];
    const float* tr   = (const float*)d_in[3];
    const float* mask = (const float*)d_in[4];
    const float* Wq   = (const float*)d_in[5];
    const float* bq   = (const float*)d_in[6];
    const float* Wkv  = (const float*)d_in[7];
    const float* bkv  = (const float*)d_in[8];
    const float* Wqp  = (const float*)d_in[9];
    const float* bqp  = (const float*)d_in[10];
    const float* Wkvp = (const float*)d_in[11];
    const float* bkvp = (const float*)d_in[12];
    const float* Wb   = (const float*)d_in[13];
    const float* bb   = (const float*)d_in[14];
    const float* hwts = (const float*)d_in[15];
    const float* Wout = (const float*)d_in[16];
    const float* bout = (const float*)d_in[17];
    float* out = (float*)d_out;

    proj_kernel<<<128, 384>>>(s, tt, tr, Wq, bq, Wkv, bkv, Wqp, bqp, Wkvp, bkvp);
    attn_kernel<<<512, 384>>>(z, mask, Wb, bb, hwts, tt, tr);
    init_out_kernel<<<512, 384>>>(bout, out);
    out_gemm_kernel<<<128, 384>>>(Wout, out);
}

// round 4
// speedup vs baseline: 1.8466x; 1.8306x over previous
#include <cuda_runtime.h>
#include <math.h>

#define NTOK 512
#define H    12
#define CZ   128
#define CS   384
#define CATD 2112   // 192 + 96*4 + 1536

// ---------------- scratch (device globals) ----------------
__device__ float g_q   [NTOK * 192];         // [n][h*16+c]
__device__ float g_qpts[NTOK * 144];         // [n][(h*4+p)*3 + x]  (global frame)
__device__ float g_ck  [12 * 30 * NTOK];     // [h][d][n] d: 0-15 k, 16-27 kpts, 28 mask
__device__ float g_vall[12 * 40 * NTOK];     // [h][d][n] d: 0-15 v, 16-39 vpts
__device__ float g_cat [NTOK * CATD];

// =================================================================================
// Kernel A: projections + rigid transform + build g_ck / g_vall (j-major layouts)
// =================================================================================
__global__ __launch_bounds__(384) void proj_kernel(
    const float* __restrict__ s,  const float* __restrict__ tt, const float* __restrict__ tr,
    const float* __restrict__ msk,
    const float* __restrict__ Wq, const float* __restrict__ bq,
    const float* __restrict__ Wkv,const float* __restrict__ bkv,
    const float* __restrict__ Wqp,const float* __restrict__ bqp,
    const float* __restrict__ Wkvp,const float* __restrict__ bkvp)
{
    __shared__ float ssh[CS * 4];        // [k][m]
    __shared__ float rawsh[4 * 1152];
    const int n0 = blockIdx.x * 4;
    const int t  = threadIdx.x;

    for (int idx = t; idx < 4 * CS; idx += 384) {
        int m = idx / CS, k = idx - m * CS;
        ssh[k * 4 + m] = s[(n0 + m) * CS + k];
    }
    __syncthreads();

    const float4* s4 = (const float4*)ssh;
    #pragma unroll
    for (int p = 0; p < 3; p++) {
        int o = p * 384 + t;
        const float* W; const float* bias; int col, width;
        if      (o < 192) { W = Wq;   bias = bq;   col = o;       width = 192; }
        else if (o < 576) { W = Wkv;  bias = bkv;  col = o - 192; width = 384; }
        else if (o < 720) { W = Wqp;  bias = bqp;  col = o - 576; width = 144; }
        else              { W = Wkvp; bias = bkvp; col = o - 720; width = 432; }
        float b0 = bias[col];
        float a0 = b0, a1 = b0, a2 = b0, a3 = b0;
        const float* Wc = W + col;
        #pragma unroll 4
        for (int k = 0; k < CS; k++) {
            float w = Wc[k * width];
            float4 sv = s4[k];
            a0 += sv.x * w; a1 += sv.y * w; a2 += sv.z * w; a3 += sv.w * w;
        }
        rawsh[0*1152 + o] = a0; rawsh[1*1152 + o] = a1;
        rawsh[2*1152 + o] = a2; rawsh[3*1152 + o] = a3;
    }
    __syncthreads();

    for (int m = 0; m < 4; m++) {
        const int n = n0 + m;
        const float* raw = rawsh + m * 1152;
        if (t < 192) {
            int h = t >> 4, c = t & 15;
            g_q[n*192 + t] = raw[t];
            g_ck  [(h*30 + c)*NTOK + n] = raw[192 + h*32 + c];        // k
            g_vall[(h*40 + c)*NTOK + n] = raw[192 + h*32 + 16 + c];   // v
        } else if (t < 240) {
            int p = t - 192;   // (h*4 + pq)
            float lx = raw[576 + p], ly = raw[576 + 48 + p], lz = raw[576 + 96 + p];
            const float* R = tr + n*9; const float* T = tt + n*3;
            float gx = R[0]*lx + R[1]*ly + R[2]*lz + T[0];
            float gy = R[3]*lx + R[4]*ly + R[5]*lz + T[1];
            float gz = R[6]*lx + R[7]*ly + R[8]*lz + T[2];
            g_qpts[n*144 + p*3 + 0] = gx;
            g_qpts[n*144 + p*3 + 1] = gy;
            g_qpts[n*144 + p*3 + 2] = gz;
        } else {
            int p = t - 240;   // (h*12 + pp)
            float lx = raw[720 + p], ly = raw[720 + 144 + p], lz = raw[720 + 288 + p];
            const float* R = tr + n*9; const float* T = tt + n*3;
            float gx = R[0]*lx + R[1]*ly + R[2]*lz + T[0];
            float gy = R[3]*lx + R[4]*ly + R[5]*lz + T[1];
            float gz = R[6]*lx + R[7]*ly + R[8]*lz + T[2];
            int h = p / 12, pp = p - h*12;
            if (pp < 4) {
                int d = 16 + pp*3;
                g_ck[(h*30 + d + 0)*NTOK + n] = gx;
                g_ck[(h*30 + d + 1)*NTOK + n] = gy;
                g_ck[(h*30 + d + 2)*NTOK + n] = gz;
            } else {
                int d = 16 + (pp - 4)*3;
                g_vall[(h*40 + d + 0)*NTOK + n] = gx;
                g_vall[(h*40 + d + 1)*NTOK + n] = gy;
                g_vall[(h*40 + d + 2)*NTOK + n] = gz;
            }
        }
    }
    __syncthreads();
    if (t < 48) {
        int m = t / 12, h = t - m*12;
        int n = n0 + m;
        g_ck[(h*30 + 28)*NTOK + n] = msk[n];
    }
}

// =================================================================================
// Kernel B: fused attention, one block per query row i. Dynamic smem ~100KB.
// =================================================================================
#define ASHO 0                 // a[12][512]                       6144
#define ZSHO 6144              // z chunk [128][132]               16896   (reused later)
#define WBTO 23040             // c2*Wb^T [12][132]                1584
#define CQSO 24624             // cq [12][32]                      384
#define CCNO 25008             // cconst[12]
#define SMEM_FLOATS 25024
#define SMEM_BYTES  (SMEM_FLOATS * 4)

__global__ __launch_bounds__(384) void attn_kernel(
    const float* __restrict__ z,   const float* __restrict__ msk,
    const float* __restrict__ Wb,  const float* __restrict__ bb,
    const float* __restrict__ hwts,const float* __restrict__ tt,
    const float* __restrict__ tr)
{
    extern __shared__ float sm[];
    float* a_sh = sm + ASHO;
    float* zsh  = sm + ZSHO;
    float* wbt  = sm + WBTO;
    float* cqs  = sm + CQSO;
    float* ccn  = sm + CCNO;

    const int i = blockIdx.x, t = threadIdx.x;
    const float mask_i = msk[i];
    const float c2 = 0.57735026918962584f;   // 1/sqrt(3)

    // ---- build cq / cconst / wbt ----
    for (int idx = t; idx < 360; idx += 384) {
        int h = idx / 30, d = idx - h*30;
        float x = hwts[h];
        float sp = (x > 20.f) ? x : log1pf(__expf(x));
        float hw = sp * 0.13608276348795434f;   // softplus * sqrt(1/54)
        float v;
        if      (d < 16)  v = 0.14433756729740643f * g_q[i*192 + h*16 + d]; // 1/sqrt(48)
        else if (d < 28)  v = g_qpts[i*144 + h*12 + (d - 16)];              // raw q_pts
        else if (d == 28) v = -0.5f * hw;
        else              v = mask_i;
        cqs[h*32 + d] = v;
    }
    if (t < 12) {
        ccn[t] = c2 * bb[t];
    }
    for (int idx = t; idx < 1536; idx += 384) {   // Wb[128][12] -> wbt[h][kk], scaled by c2
        int kk = idx / 12, h = idx - kk*12;
        wbt[h*132 + kk] = c2 * Wb[idx];
    }
    __syncthreads();

    const size_t zbase = (size_t)i * NTOK * CZ;

    // ---- Phase 1: bias GEMM  a_sh[h][j] = c2 * z[i,j,:].Wb[:,h] ----
    {
        const int ks = t & 3, g = t >> 2;         // 96 groups x 4 ksplits
        const int hg = g % 3, jq = g / 3;         // jq 0..31 (j-quad), hg: 4-head group
        for (int cch = 0; cch < 4; cch++) {
            const int j0 = cch * 128;
            for (int idx = t; idx < 4096; idx += 384) {          // load 128x128 z chunk
                int r = idx >> 5, c4 = idx & 31;
                float4 zv = *(const float4*)(z + zbase + (size_t)(j0 + r)*128 + c4*4);
                *(float4*)(zsh + r*132 + c4*4) = zv;
            }
            __syncthreads();
            float acc[4][4];
            #pragma unroll
            for (int a = 0; a < 4; a++)
                #pragma unroll
                for (int b = 0; b < 4; b++) acc[a][b] = 0.f;
            #pragma unroll
            for (int it = 0; it < 8; it++) {
                const int kq = it*4 + ks;
                float4 z4[4], w4[4];
                #pragma unroll
                for (int jj = 0; jj < 4; jj++)
                    z4[jj] = *(const float4*)(zsh + (jq*4 + jj)*132 + kq*4);
                #pragma unroll
                for (int hh = 0; hh < 4; hh++)
                    w4[hh] = *(const float4*)(wbt + (hg*4 + hh)*132 + kq*4);
                #pragma unroll
                for (int jj = 0; jj < 4; jj++)
                    #pragma unroll
                    for (int hh = 0; hh < 4; hh++) {
                        acc[jj][hh] += z4[jj].x * w4[hh].x;
                        acc[jj][hh] += z4[jj].y * w4[hh].y;
                        acc[jj][hh] += z4[jj].z * w4[hh].z;
                        acc[jj][hh] += z4[jj].w * w4[hh].w;
                    }
            }
            #pragma unroll
            for (int jj = 0; jj < 4; jj++)
                #pragma unroll
                for (int hh = 0; hh < 4; hh++) {
                    float v = acc[jj][hh];
                    v += __shfl_xor_sync(0xffffffffu, v, 1);
                    v += __shfl_xor_sync(0xffffffffu, v, 2);
                    if (ks == 0)
                        a_sh[(hg*4 + hh)*512 + j0 + jq*4 + jj] = v;
                }
            __syncthreads();
        }
    }

    // ---- Phase 1b: add qk + point-dist (direct (q-k)^2) + mask ----
    {
        const int w = t >> 5, lane = t & 31;      // warp w owns head w
        float cq[16], qp[12];
        #pragma unroll
        for (int d = 0; d < 16; d++) cq[d] = cqs[w*32 + d];
        #pragma unroll
        for (int p = 0; p < 12; p++) qp[p] = cqs[w*32 + 16 + p];
        const float nh = cqs[w*32 + 28];          // -0.5*hw
        const float mi = cqs[w*32 + 29];          // mask_i
        const float cst = ccn[w];
        #pragma unroll
        for (int r = 0; r < 4; r++) {
            const int j = r*128 + lane*4;
            const float* ckb = g_ck + (size_t)w*30*NTOK + j;
            float4 av; av.x = cst; av.y = cst; av.z = cst; av.w = cst;
            #pragma unroll
            for (int d = 0; d < 16; d++) {
                float4 kv = *(const float4*)(ckb + d*NTOK);
                av.x += cq[d]*kv.x; av.y += cq[d]*kv.y;
                av.z += cq[d]*kv.z; av.w += cq[d]*kv.w;
            }
            float4 d2; d2.x = d2.y = d2.z = d2.w = 0.f;
            #pragma unroll
            for (int p = 0; p < 12; p++) {
                float4 kv = *(const float4*)(ckb + (16 + p)*NTOK);
                float dx = qp[p] - kv.x; d2.x += dx*dx;
                float dy = qp[p] - kv.y; d2.y += dy*dy;
                float dz = qp[p] - kv.z; d2.z += dz*dz;
                float dw = qp[p] - kv.w; d2.w += dw*dw;
            }
            av.x += nh*d2.x; av.y += nh*d2.y; av.z += nh*d2.z; av.w += nh*d2.w;
            // mask term: 1e5*(mask_i*msk_j - 1)  (exact 0 when both masks are 1)
            float4 mj = *(const float4*)(ckb + 28*NTOK);
            av.x += 100000.0f * fmaf(mi, mj.x, -1.0f);
            av.y += 100000.0f * fmaf(mi, mj.y, -1.0f);
            av.z += 100000.0f * fmaf(mi, mj.z, -1.0f);
            av.w += 100000.0f * fmaf(mi, mj.w, -1.0f);
            float4 cur = *(const float4*)(a_sh + w*512 + j);
            cur.x += av.x; cur.y += av.y; cur.z += av.z; cur.w += av.w;
            *(float4*)(a_sh + w*512 + j) = cur;
        }
    }
    __syncthreads();

    // ---- Phase 2: softmax (warp w -> head w) ----
    {
        const int w = t >> 5, lane = t & 31;
        float* row = a_sh + w * 512;
        float mx = -1e30f;
        for (int j = lane; j < 512; j += 32) mx = fmaxf(mx, row[j]);
        #pragma unroll
        for (int o = 16; o; o >>= 1) mx = fmaxf(mx, __shfl_xor_sync(0xffffffffu, mx, o));
        float ssum = 0.f;
        for (int j = lane; j < 512; j += 32) { float e = __expf(row[j] - mx); row[j] = e; ssum += e; }
        #pragma unroll
        for (int o = 16; o; o >>= 1) ssum += __shfl_xor_sync(0xffffffffu, ssum, o);
        float inv = 1.0f / ssum;
        for (int j = lane; j < 512; j += 32) row[j] *= inv;
    }
    __syncthreads();

    // ---- Phase 3a: o and raw o_pt (warp per output, lanes along j) ----
    {
        const int w = t >> 5, lane = t & 31;
        float* optbuf = zsh;                       // 288 floats
        #pragma unroll 4
        for (int r = 0; r < 40; r++) {
            const int task = r*12 + w;             // 480 tasks
            const int h = task / 40, d = task - h*40;
            const float* vb = g_vall + (size_t)(h*40 + d)*NTOK;
            const float* ab = a_sh + h*512;
            float4 acc4; acc4.x = acc4.y = acc4.z = acc4.w = 0.f;
            #pragma unroll
            for (int it = 0; it < 4; it++) {
                float4 v4 = *(const float4*)(vb + it*128 + lane*4);
                float4 a4 = *(const float4*)(ab + it*128 + lane*4);
                acc4.x += v4.x*a4.x; acc4.y += v4.y*a4.y;
                acc4.z += v4.z*a4.z; acc4.w += v4.w*a4.w;
            }
            float sres = acc4.x + acc4.y + acc4.z + acc4.w;
            #pragma unroll
            for (int o = 16; o; o >>= 1) sres += __shfl_xor_sync(0xffffffffu, sres, o);
            if (lane == 0) {
                if (d < 16) g_cat[i*CATD + h*16 + d] = sres;
                else        optbuf[h*24 + (d - 16)] = sres;
            }
        }
    }
    __syncthreads();

    // ---- Phase 3b: inverse rigid transform + norms ----
    if (t < 96) {
        const float* optbuf = zsh;
        float gx = optbuf[t*3], gy = optbuf[t*3 + 1], gz = optbuf[t*3 + 2];
        const float* R = tr + i*9; const float* T = tt + i*3;
        float dx = gx - T[0], dy = gy - T[1], dz = gz - T[2];
        float lx = R[0]*dx + R[3]*dy + R[6]*dz;
        float ly = R[1]*dx + R[4]*dy + R[7]*dz;
        float lz = R[2]*dx + R[5]*dy + R[8]*dz;
        float* cr = g_cat + i*CATD;
        cr[192 + t] = lx; cr[288 + t] = ly; cr[384 + t] = lz;
        cr[480 + t] = sqrtf(lx*lx + ly*ly + lz*lz + 1e-8f);
    }

    // ---- Phase 3c: o_pair with 4c x 4h register tile ----
    {
        const int cq4 = t & 31;                  // c-quad
        const int w   = t >> 5;
        const int hg  = w % 3, js = w / 3;       // js: j-split 0..3
        float acc[4][4];                          // [hh][cc]
        #pragma unroll
        for (int a = 0; a < 4; a++)
            #pragma unroll
            for (int b = 0; b < 4; b++) acc[a][b] = 0.f;
        #pragma unroll 2
        for (int jqq = 0; jqq < 32; jqq++) {
            const int j = js*128 + jqq*4;
            float4 z4[4], a4[4];
            #pragma unroll
            for (int jj = 0; jj < 4; jj++)
                z4[jj] = *(const float4*)(z + zbase + (size_t)(j + jj)*128 + cq4*4);
            #pragma unroll
            for (int hh = 0; hh < 4; hh++)
                a4[hh] = *(const float4*)(a_sh + (hg*4 + hh)*512 + j);
            #pragma unroll
            for (int hh = 0; hh < 4; hh++) {
                acc[hh][0] += a4[hh].x*z4[0].x + a4[hh].y*z4[1].x + a4[hh].z*z4[2].x + a4[hh].w*z4[3].x;
                acc[hh][1] += a4[hh].x*z4[0].y + a4[hh].y*z4[1].y + a4[hh].z*z4[2].y + a4[hh].w*z4[3].y;
                acc[hh][2] += a4[hh].x*z4[0].z + a4[hh].y*z4[1].z + a4[hh].z*z4[2].z + a4[hh].w*z4[3].z;
                acc[hh][3] += a4[hh].x*z4[0].w + a4[hh].y*z4[1].w + a4[hh].z*z4[2].w + a4[hh].w*z4[3].w;
            }
        }
        float* part = zsh + 512;                 // [4js][12h][128c] = 6144 floats
        #pragma unroll
        for (int hh = 0; hh < 4; hh++)
            #pragma unroll
            for (int cc = 0; cc < 4; cc++)
                part[js*1536 + (hg*4 + hh)*128 + cq4*4 + cc] = acc[hh][cc];
    }
    __syncthreads();
    {
        const float* part = zsh + 512;
        for (int idx = t; idx < 1536; idx += 384) {
            float v = part[idx] + part[1536 + idx] + part[3072 + idx] + part[4608 + idx];
            g_cat[i*CATD + 576 + idx] = v;
        }
    }
}

// =================================================================================
// Kernel C0: out = bout
// =================================================================================
__global__ void init_out_kernel(const float* __restrict__ bout, float* __restrict__ out)
{
    out[blockIdx.x * 384 + threadIdx.x] = bout[threadIdx.x];
}

// =================================================================================
// Kernel C1: out += cat @ Wout. 16 k-splits x 32 m-tiles = 512 blocks.
// =================================================================================
__global__ __launch_bounds__(384) void out_gemm_kernel(
    const float* __restrict__ Wout, float* __restrict__ out)
{
    __shared__ float csh[132 * 16];     // [kk][m]
    const int bx = blockIdx.x;
    const int rt = bx & 31, ks = bx >> 5;
    const int i0 = rt * 16, k0 = ks * 132;
    const int t  = threadIdx.x;

    for (int idx = t; idx < 132 * 16; idx += 384) {
        int row = idx / 132, kk = idx - row * 132;
        csh[kk*16 + row] = g_cat[(i0 + row) * CATD + k0 + kk];
    }
    __syncthreads();

    float acc[16];
    #pragma unroll
    for (int m = 0; m < 16; m++) acc[m] = 0.f;

    const float* Wp = Wout + (size_t)k0 * 384 + t;
    float w = Wp[0];
    for (int kk = 0; kk < 132; kk++) {
        float wn = (kk < 131) ? Wp[(size_t)(kk + 1) * 384] : 0.f;
        const float4* cp = (const float4*)(csh + kk * 16);
        float4 c0 = cp[0], c1 = cp[1], c2 = cp[2], c3 = cp[3];
        acc[0]  += c0.x*w; acc[1]  += c0.y*w; acc[2]  += c0.z*w; acc[3]  += c0.w*w;
        acc[4]  += c1.x*w; acc[5]  += c1.y*w; acc[6]  += c1.z*w; acc[7]  += c1.w*w;
        acc[8]  += c2.x*w; acc[9]  += c2.y*w; acc[10] += c2.z*w; acc[11] += c2.w*w;
        acc[12] += c3.x*w; acc[13] += c3.y*w; acc[14] += c3.z*w; acc[15] += c3.w*w;
        w = wn;
    }
    #pragma unroll
    for (int m = 0; m < 16; m++)
        atomicAdd(&out[(i0 + m) * 384 + t], acc[m]);
}

// =================================================================================
extern "C" void kernel_launch(void* const* d_in, const int* in_sizes, int n_in,
                              void* d_out, int out_size)
{
    (void)in_sizes; (void)n_in; (void)out_size;
    const float* s    = (const float*)d_in[0];
    const float* z    = (const float*)d_in[1];
    const float* tt   = (const float*)d_in[2];
    const float* tr   = (const float*)d_in[3];
    const float* mask = (const float*)d_in[4];
    const float* Wq   = (const float*)d_in[5];
    const float* bq   = (const float*)d_in[6];
    const float* Wkv  = (const float*)d_in[7];
    const float* bkv  = (const float*)d_in[8];
    const float* Wqp  = (const float*)d_in[9];
    const float* bqp  = (const float*)d_in[10];
    const float* Wkvp = (const float*)d_in[11];
    const float* bkvp = (const float*)d_in[12];
    const float* Wb   = (const float*)d_in[13];
    const float* bb   = (const float*)d_in[14];
    const float* hwts = (const float*)d_in[15];
    const float* Wout = (const float*)d_in[16];
    const float* bout = (const float*)d_in[17];
    float* out = (float*)d_out;

    cudaFuncSetAttribute(attn_kernel, cudaFuncAttributeMaxDynamicSharedMemorySize, SMEM_BYTES);

    proj_kernel<<<128, 384>>>(s, tt, tr, mask, Wq, bq, Wkv, bkv, Wqp, bqp, Wkvp, bkvp);
    attn_kernel<<<512, 384, SMEM_BYTES>>>(z, mask, Wb, bb, hwts, tt, tr);
    init_out_kernel<<<512, 384>>>(bout, out);
    out_gemm_kernel<<<512, 384>>>(Wout, out);
}